// round 14
// baseline (speedup 1.0000x reference)
#include <cuda_runtime.h>
#include <cuda_bf16.h>
#include <cstdint>

// Problem shapes (fixed by setup_inputs)
constexpr int T_TOK = 8192;
constexpr int H_DIM = 2048;
constexpr int I_DIM = 8192;
constexpr int N_EXP = 8;
constexpr int CAP   = 1280;

constexpr int MT_N  = CAP / 128;      // 10 m-tiles per expert
constexpr int KI1   = H_DIM / 32;     // 64  k-iters gemm1
constexpr int KI2   = I_DIM / 32;     // 256 k-iters gemm2
constexpr int NT1   = I_DIM / 128;    // 64  n-tiles gemm1
constexpr int NT2   = H_DIM / 128;    // 16  n-tiles gemm2

constexpr int PWI_BLKS  = NT1 * KI1 * N_EXP;    // 32768 prep_wi CTAs
constexpr int GATE_BLKS = T_TOK / 8;            // 1024
constexpr int ZERO_BLKS = 1024;                 // zero d_out

// ---------------------------------------------------------------------------
// Device-global scratch. Tile = 4096 u32 = 16KB:
//   A-tile: [A_hi 2048 u32][A_lo 2048 u32], m16n8k16 bf16 A-fragment order
//   B-tile: [B_hi 2048 u32][B_lo 2048 u32], m16n8k16 bf16 B-fragment order
// NOTE: device-code references only (host-side use binds the host shadow).
// ---------------------------------------------------------------------------
__device__ uint32_t g_wiP[(size_t)N_EXP * NT1 * KI1 * 4096];  // 512MiB
__device__ uint32_t g_woP[(size_t)N_EXP * NT2 * KI2 * 4096];  // 512MiB
__device__ uint32_t g_aP [(size_t)N_EXP * MT_N * KI1 * 4096]; //  80MiB
__device__ uint32_t g_hP [(size_t)N_EXP * MT_N * KI2 * 4096]; // 320MiB
__device__ int   g_top1[T_TOK];
__device__ float g_wt[T_TOK];
__device__ int   g_token_of_slot[N_EXP * CAP];
__device__ float g_slot_wt[N_EXP * CAP];
__device__ int   g_counts[N_EXP];

// ---------------------------------------------------------------------------
// helpers
// ---------------------------------------------------------------------------
__device__ __forceinline__ void mma_bf16(float* c,
                                         uint32_t a0, uint32_t a1, uint32_t a2, uint32_t a3,
                                         uint32_t b0, uint32_t b1) {
    asm volatile(
        "mma.sync.aligned.m16n8k16.row.col.f32.bf16.bf16.f32 "
        "{%0,%1,%2,%3}, {%4,%5,%6,%7}, {%8,%9}, {%0,%1,%2,%3};"
        : "+f"(c[0]), "+f"(c[1]), "+f"(c[2]), "+f"(c[3])
        : "r"(a0), "r"(a1), "r"(a2), "r"(a3), "r"(b0), "r"(b1));
}
// split x,y into bf16 hi/lo pairs; returns packed hi (x in low half), sets lo
__device__ __forceinline__ uint32_t split2(float x, float y, uint32_t& lo) {
    __nv_bfloat16 hx = __float2bfloat16_rn(x);
    __nv_bfloat16 hy = __float2bfloat16_rn(y);
    __nv_bfloat16 lx = __float2bfloat16_rn(x - __bfloat162float(hx));
    __nv_bfloat16 ly = __float2bfloat16_rn(y - __bfloat162float(hy));
    lo = (uint32_t)*(unsigned short*)&lx
       | ((uint32_t)*(unsigned short*)&ly << 16);
    return (uint32_t)*(unsigned short*)&hx
         | ((uint32_t)*(unsigned short*)&hy << 16);
}
__device__ __forceinline__ uint32_t smem_u32(const void* p) {
    uint32_t a;
    asm("{ .reg .u64 t; cvta.to.shared.u64 t, %1; cvt.u32.u64 %0, t; }"
        : "=r"(a) : "l"(p));
    return a;
}
__device__ __forceinline__ void mbar_init(uint32_t a, uint32_t cnt) {
    asm volatile("mbarrier.init.shared.b64 [%0], %1;" :: "r"(a), "r"(cnt) : "memory");
}
__device__ __forceinline__ void mbar_expect(uint32_t a, uint32_t tx) {
    asm volatile("mbarrier.arrive.expect_tx.shared.b64 _, [%0], %1;"
                 :: "r"(a), "r"(tx) : "memory");
}
__device__ __forceinline__ void mbar_arrive(uint32_t a) {
    asm volatile("mbarrier.arrive.shared.b64 _, [%0];" :: "r"(a) : "memory");
}
__device__ __forceinline__ void bulk_g2s(uint32_t dst, const void* src,
                                         uint32_t bytes, uint32_t mbar) {
    asm volatile(
        "cp.async.bulk.shared::cta.global.mbarrier::complete_tx::bytes "
        "[%0], [%1], %2, [%3];"
        :: "r"(dst), "l"(src), "r"(bytes), "r"(mbar) : "memory");
}
__device__ __forceinline__ void mbar_wait(uint32_t a, uint32_t ph) {
    asm volatile(
        "{\n\t.reg .pred P;\n\t"
        "W%=:\n\t"
        "mbarrier.try_wait.parity.shared.b64 P, [%0], %1;\n\t"
        "@!P bra W%=;\n\t}"
        :: "r"(a), "r"(ph) : "memory");
}
__device__ __forceinline__ float gelu_exact(float x) {
    return 0.5f * x * (1.f + erff(x * 0.7071067811865475f));
}

// B-tile permute: ts = [32][136] fp32 (32 k x 128 n), d = one 4096-u32 tile.
// B-frag: b0={B[2c][n],B[2c+1][n]}, b1={B[2c+8][n],B[2c+9][n]}, per kk (k16).
__device__ __forceinline__ void permute_store(const float* ts, uint32_t* d, int t) {
#pragma unroll
    for (int j = 0; j < 4; j++) {
        int q  = t + 256 * j;          // uint2 index, 0..1023
        int ln = q & 31;
        int g  = q >> 5;               // 0..31
        int nt = g & 15, kk = g >> 4;  // kk 0..1
        int n  = nt * 8 + (ln >> 2);
        int c  = ln & 3;
        int k0 = kk * 16 + 2 * c;
        uint32_t l0, l1;
        uint2 hi, lo;
        hi.x = split2(ts[k0 * 136 + n],       ts[(k0 + 1) * 136 + n], l0);
        hi.y = split2(ts[(k0 + 8) * 136 + n], ts[(k0 + 9) * 136 + n], l1);
        lo.x = l0; lo.y = l1;
        *(uint2*)(d + (size_t)q * 2)        = hi;
        *(uint2*)(d + 2048 + (size_t)q * 2) = lo;
    }
}

// ---------------------------------------------------------------------------
// Launch 1: fused prep_wi + gating + zero(d_out)
// ---------------------------------------------------------------------------
__global__ __launch_bounds__(256)
void prep_wi_gate(const float* __restrict__ tokens,
                  const float* __restrict__ gw,
                  const float* __restrict__ wi,
                  float* __restrict__ outp) {
    __shared__ float ts[32 * 136];
    int bid = blockIdx.x;
    int t = threadIdx.x;
    if (bid < PWI_BLKS) {
        int e = bid >> 12;
        int rem = bid & 4095;
        int bx = rem >> 6;
        int by = rem & 63;
        int n0 = bx * 128, k0 = by * 32;
        const float* s = wi + ((size_t)e * H_DIM + k0) * I_DIM + n0;
#pragma unroll
        for (int i = 0; i < 16; i++) {
            int f = t + 256 * i;
            int r = f >> 7, c = f & 127;
            ts[r * 136 + c] = s[(size_t)r * I_DIM + c];
        }
        __syncthreads();
        uint32_t* d = g_wiP + (((size_t)e * 64 + bx) * 64 + by) * 4096;
        permute_store(ts, d, t);
    } else if (bid < PWI_BLKS + GATE_BLKS) {
        int warp = t >> 5;
        int lane = t & 31;
        int tok = (bid - PWI_BLKS) * 8 + warp;
        if (tok >= T_TOK) return;
        const float* x = tokens + (size_t)tok * H_DIM;
        float acc[N_EXP];
#pragma unroll
        for (int e = 0; e < N_EXP; e++) acc[e] = 0.f;
        for (int k = lane; k < H_DIM; k += 32) {
            float xv = x[k];
#pragma unroll
            for (int e = 0; e < N_EXP; e++)
                acc[e] = fmaf(xv, gw[e * H_DIM + k], acc[e]);
        }
#pragma unroll
        for (int off = 16; off; off >>= 1)
#pragma unroll
            for (int e = 0; e < N_EXP; e++)
                acc[e] += __shfl_xor_sync(0xffffffffu, acc[e], off);
        if (lane == 0) {
            int best = 0; float bv = acc[0];
#pragma unroll
            for (int e = 1; e < N_EXP; e++)
                if (acc[e] > bv) { bv = acc[e]; best = e; }
            float s = 0.f;
#pragma unroll
            for (int e = 0; e < N_EXP; e++) s += expf(acc[e] - bv);
            g_top1[tok] = best;
            g_wt[tok]   = 1.f / s;
        }
    } else {
        int zb = bid - (PWI_BLKS + GATE_BLKS);
        float4* dst = (float4*)outp + (size_t)zb * 4096 + t;
        float4 z = make_float4(0.f, 0.f, 0.f, 0.f);
#pragma unroll
        for (int i = 0; i < 16; i++) dst[i * 256] = z;
    }
}

// ---------------------------------------------------------------------------
// Launch 2: rank_kernel (verified)
// ---------------------------------------------------------------------------
__global__ void rank_kernel() {
    __shared__ int sc[1024][N_EXP];
    int tid = threadIdx.x;
    for (int s = tid; s < N_EXP * CAP; s += 1024) g_token_of_slot[s] = -1;
    int el[8], cnt[N_EXP];
#pragma unroll
    for (int e = 0; e < N_EXP; e++) cnt[e] = 0;
#pragma unroll
    for (int i = 0; i < 8; i++) {
        int t = tid * 8 + i;
        int e = g_top1[t];
        el[i] = e; cnt[e]++;
    }
#pragma unroll
    for (int e = 0; e < N_EXP; e++) sc[tid][e] = cnt[e];
    __syncthreads();
    for (int off = 1; off < 1024; off <<= 1) {
        int v[N_EXP];
        if (tid >= off)
#pragma unroll
            for (int e = 0; e < N_EXP; e++) v[e] = sc[tid - off][e];
        __syncthreads();
        if (tid >= off)
#pragma unroll
            for (int e = 0; e < N_EXP; e++) sc[tid][e] += v[e];
        __syncthreads();
    }
    int base[N_EXP];
#pragma unroll
    for (int e = 0; e < N_EXP; e++) base[e] = sc[tid][e] - cnt[e];
#pragma unroll
    for (int i = 0; i < 8; i++) {
        int t = tid * 8 + i;
        int e = el[i];
        int r = base[e]++;
        if (r < CAP) {
            g_token_of_slot[e * CAP + r] = t;
            g_slot_wt[e * CAP + r]       = g_wt[t];
        }
    }
    if (tid == 1023)
#pragma unroll
        for (int e = 0; e < N_EXP; e++) g_counts[e] = min(sc[1023][e], CAP);
}

// ---------------------------------------------------------------------------
// Launch 3: dispatch_aP: gather tokens -> bf16 hi/lo A-fragment tiles
// A-frag: a0={A[r][2c],A[r][2c+1]}, a1={A[r+8][..]}, a2={A[r][2c+8],+9},
//         a3={A[r+8][2c+8],+9}, per kk (k16 step), mt (16-row tile).
// ---------------------------------------------------------------------------
__global__ __launch_bounds__(256)
void dispatch_aP(const float* __restrict__ tokens) {
    __shared__ float ts[128][36];
    int e = blockIdx.z, mT = blockIdx.y, kI = blockIdx.x;
    int k0 = kI * 32;
    int t = threadIdx.x;
#pragma unroll
    for (int i = 0; i < 4; i++) {
        int f = t + 256 * i;
        int row = f >> 3, c4 = (f & 7) * 4;
        int tok = g_token_of_slot[e * CAP + mT * 128 + row];
        float4 v = (tok >= 0)
                 ? *(const float4*)(tokens + (size_t)tok * H_DIM + k0 + c4)
                 : make_float4(0.f, 0.f, 0.f, 0.f);
        *(float4*)&ts[row][c4] = v;
    }
    __syncthreads();
    uint32_t* d = g_aP + (((size_t)e * MT_N + mT) * KI1 + kI) * 4096;
    int ln = t & 31, mt = t >> 5;
    int r = ln >> 2, c = ln & 3;
    int row = mt * 16 + r;
#pragma unroll
    for (int kk = 0; kk < 2; kk++) {
        int kb = kk * 16 + 2 * c;
        uint4 hi, lo;
        hi.x = split2(ts[row][kb],         ts[row][kb + 1],         lo.x);
        hi.y = split2(ts[row + 8][kb],     ts[row + 8][kb + 1],     lo.y);
        hi.z = split2(ts[row][kb + 8],     ts[row][kb + 9],         lo.z);
        hi.w = split2(ts[row + 8][kb + 8], ts[row + 8][kb + 9],     lo.w);
        size_t o = (size_t)((kk * 8 + mt) * 32 + ln) * 4;
        *(uint4*)(d + o)        = hi;
        *(uint4*)(d + 2048 + o) = lo;
    }
}

// ---------------------------------------------------------------------------
// Launch 5: prep_wo (standalone, high occupancy)
// ---------------------------------------------------------------------------
__global__ __launch_bounds__(256)
void prep_wo(const float* __restrict__ wo) {
    __shared__ float ts[32 * 136];
    int e = blockIdx.z;
    int n0 = blockIdx.x * 128, k0 = blockIdx.y * 32;
    const float* s = wo + ((size_t)e * I_DIM + k0) * H_DIM + n0;
    int t = threadIdx.x;
#pragma unroll
    for (int i = 0; i < 16; i++) {
        int f = t + 256 * i;
        int r = f >> 7, c = f & 127;
        ts[r * 136 + c] = s[(size_t)r * H_DIM + c];
    }
    __syncthreads();
    uint32_t* d = g_woP + (((size_t)e * NT2 + blockIdx.x) * KI2 + blockIdx.y) * 4096;
    permute_store(ts, d, t);
}

// ---------------------------------------------------------------------------
// GEMM core: 128x128x32, 3-stage TMA-bulk pipeline, full/empty mbarriers,
// bf16x3 compensated MMA (m16n8k16). Stage 32KB: [A_hi|A_lo|B_hi|B_lo] 8KB ea.
// ---------------------------------------------------------------------------
#define STG_B 32768

struct MmaCtx {
    uint32_t sbase;
    int lane, wm, wn;
};

__device__ __forceinline__ void consume_stage(const MmaCtx& cx, int s,
                                              float acc[4][4][4]) {
    uint32_t aB = cx.sbase + s * STG_B;
    uint32_t bB = aB + 16384;
#pragma unroll
    for (int kk = 0; kk < 2; kk++) {
        uint4 ah[4], al[4];
        uint2 bh[4], bl[4];
#pragma unroll
        for (int mt = 0; mt < 4; mt++) {
            uint32_t addr = aB + (((kk * 8 + cx.wm * 4 + mt) * 32 + cx.lane) << 4);
            asm volatile("ld.shared.v4.b32 {%0,%1,%2,%3}, [%4];"
                         : "=r"(ah[mt].x), "=r"(ah[mt].y),
                           "=r"(ah[mt].z), "=r"(ah[mt].w) : "r"(addr));
        }
#pragma unroll
        for (int nt = 0; nt < 4; nt++) {
            uint32_t addr = bB + (((kk * 16 + cx.wn * 4 + nt) * 32 + cx.lane) << 3);
            asm volatile("ld.shared.v2.b32 {%0,%1}, [%2];"
                         : "=r"(bh[nt].x), "=r"(bh[nt].y) : "r"(addr));
        }
        // hi x hi
#pragma unroll
        for (int mt = 0; mt < 4; mt++)
#pragma unroll
            for (int nt = 0; nt < 4; nt++)
                mma_bf16(acc[mt][nt], ah[mt].x, ah[mt].y, ah[mt].z, ah[mt].w,
                         bh[nt].x, bh[nt].y);
        // lo x hi
#pragma unroll
        for (int mt = 0; mt < 4; mt++) {
            uint32_t addr = aB + 8192
                          + (((kk * 8 + cx.wm * 4 + mt) * 32 + cx.lane) << 4);
            asm volatile("ld.shared.v4.b32 {%0,%1,%2,%3}, [%4];"
                         : "=r"(al[mt].x), "=r"(al[mt].y),
                           "=r"(al[mt].z), "=r"(al[mt].w) : "r"(addr));
        }
#pragma unroll
        for (int mt = 0; mt < 4; mt++)
#pragma unroll
            for (int nt = 0; nt < 4; nt++)
                mma_bf16(acc[mt][nt], al[mt].x, al[mt].y, al[mt].z, al[mt].w,
                         bh[nt].x, bh[nt].y);
        // hi x lo
#pragma unroll
        for (int nt = 0; nt < 4; nt++) {
            uint32_t addr = bB + 8192
                          + (((kk * 16 + cx.wn * 4 + nt) * 32 + cx.lane) << 3);
            asm volatile("ld.shared.v2.b32 {%0,%1}, [%2];"
                         : "=r"(bl[nt].x), "=r"(bl[nt].y) : "r"(addr));
        }
#pragma unroll
        for (int mt = 0; mt < 4; mt++)
#pragma unroll
            for (int nt = 0; nt < 4; nt++)
                mma_bf16(acc[mt][nt], ah[mt].x, ah[mt].y, ah[mt].z, ah[mt].w,
                         bl[nt].x, bl[nt].y);
    }
}

// thread0 fills stage s with k-iter `it` tiles via 2 bulk copies
__device__ __forceinline__ void fill_stage(uint32_t sbase, uint32_t mbar_base,
                                           int s, const uint32_t* aSrc,
                                           const uint32_t* bSrc, int it) {
    uint32_t mb = mbar_base + s * 8;
    uint32_t st = sbase + s * STG_B;
    mbar_expect(mb, 32768);
    bulk_g2s(st,         aSrc + (size_t)it * 4096, 16384, mb);
    bulk_g2s(st + 16384, bSrc + (size_t)it * 4096, 16384, mb);
}

// shared mainloop: full/empty mbarrier pipeline (R12, verified)
template <int KI>
__device__ __forceinline__ void gemm_mainloop(const MmaCtx& cx, uint32_t mbb,
                                              const uint32_t* aSrc,
                                              const uint32_t* bSrc,
                                              int t, float acc[4][4][4]) {
    if (t == 0) {
#pragma unroll
        for (int s = 0; s < 3; s++) {
            mbar_init(mbb + s * 8, 1);        // full: tx-based
            mbar_init(mbb + 24 + s * 8, 8);   // empty: 8 warp arrivals
        }
    }
    __syncthreads();
    if (t == 0) {
#pragma unroll
        for (int p = 0; p < 3; p++) fill_stage(cx.sbase, mbb, p, aSrc, bSrc, p);
    }
    for (int it = 0; it < KI; ++it) {
        int s = it % 3;
        uint32_t ph = (uint32_t)((it / 3) & 1);
        mbar_wait(mbb + s * 8, ph);
        consume_stage(cx, s, acc);
        if (cx.lane == 0) mbar_arrive(mbb + 24 + s * 8);
        if (t == 0 && it + 3 < KI) {
            mbar_wait(mbb + 24 + s * 8, ph);      // all 8 warps drained stage s
            fill_stage(cx.sbase, mbb, s, aSrc, bSrc, it + 3);
        }
    }
}

// ---------------------------------------------------------------------------
// Launch 4 (ncu slot): GEMM1: g_aP @ g_wiP -> gelu -> g_hP. mT fastest.
// ---------------------------------------------------------------------------
__global__ __launch_bounds__(256, 2)
void gemm1_tc(float* dummy) {
    extern __shared__ char smem[];
    __shared__ __align__(8) uint64_t mbs[6];
    uint32_t sbase = smem_u32(smem);
    uint32_t mbb   = smem_u32(mbs);

    int e = blockIdx.z;
    int cnt = g_counts[e];
    int mT = blockIdx.x;
    if (mT * 128 >= cnt) return;
    int nT = blockIdx.y;

    int t = threadIdx.x;
    MmaCtx cx;
    cx.sbase = sbase;
    cx.lane = t & 31;
    int w = t >> 5;
    cx.wm = w >> 2; cx.wn = w & 3;

    const uint32_t* aSrc = g_aP  + (((size_t)e * MT_N + mT) * KI1) * 4096;
    const uint32_t* bSrc = g_wiP + (((size_t)e * NT1 + nT) * KI1) * 4096;

    float acc[4][4][4];
#pragma unroll
    for (int a = 0; a < 4; a++)
#pragma unroll
        for (int b = 0; b < 4; b++)
#pragma unroll
            for (int c = 0; c < 4; c++) acc[a][b][c] = 0.f;

    gemm_mainloop<KI1>(cx, mbb, aSrc, bSrc, t, acc);
    __syncthreads();   // all warps done with all stages before smem reuse

    // epilogue: gelu -> bf16 hi/lo A-fragment tiles in g_hP via smem bounce
    float* eb = (float*)smem;   // [128][68]
    int ln = cx.lane;
    int rr = ln >> 2, bb = ln & 3;
#pragma unroll
    for (int half = 0; half < 2; half++) {
        if ((cx.wn >> 1) == half) {
            int colbase = (cx.wn & 1) * 32;
#pragma unroll
            for (int mt = 0; mt < 4; mt++) {
                int row = cx.wm * 64 + mt * 16 + rr;
#pragma unroll
                for (int nt = 0; nt < 4; nt++) {
                    int col = colbase + nt * 8 + 2 * bb;
                    float2 v0, v1;
                    v0.x = gelu_exact(acc[mt][nt][0]);
                    v0.y = gelu_exact(acc[mt][nt][1]);
                    v1.x = gelu_exact(acc[mt][nt][2]);
                    v1.y = gelu_exact(acc[mt][nt][3]);
                    *(float2*)&eb[row * 68 + col]       = v0;
                    *(float2*)&eb[(row + 8) * 68 + col] = v1;
                }
            }
        }
        __syncthreads();
        int mt8 = t >> 5;
        int row = mt8 * 16 + rr;
#pragma unroll
        for (int kl = 0; kl < 2; kl++) {
            int kI = nT * 4 + half * 2 + kl;
            uint32_t* d = g_hP + (((size_t)e * MT_N + mT) * KI2 + kI) * 4096;
#pragma unroll
            for (int kk = 0; kk < 2; kk++) {
                int cb = kl * 32 + kk * 16 + 2 * bb;
                uint4 hi, lo;
                hi.x = split2(eb[row * 68 + cb],           eb[row * 68 + cb + 1],           lo.x);
                hi.y = split2(eb[(row + 8) * 68 + cb],     eb[(row + 8) * 68 + cb + 1],     lo.y);
                hi.z = split2(eb[row * 68 + cb + 8],       eb[row * 68 + cb + 9],           lo.z);
                hi.w = split2(eb[(row + 8) * 68 + cb + 8], eb[(row + 8) * 68 + cb + 9],     lo.w);
                size_t o = (size_t)((kk * 8 + mt8) * 32 + ln) * 4;
                *(uint4*)(d + o)        = hi;
                *(uint4*)(d + 2048 + o) = lo;
            }
        }
        __syncthreads();
    }
}

// ---------------------------------------------------------------------------
// Launch 6: GEMM2: g_hP @ g_woP -> weight-scaled scatter to out. mT fastest.
// ---------------------------------------------------------------------------
__global__ __launch_bounds__(256, 2)
void gemm2_tc(float* __restrict__ outp) {
    extern __shared__ char smem[];
    __shared__ __align__(8) uint64_t mbs[6];
    uint32_t sbase = smem_u32(smem);
    uint32_t mbb   = smem_u32(mbs);

    int e = blockIdx.z;
    int cnt = g_counts[e];
    int mT = blockIdx.x;
    if (mT * 128 >= cnt) return;
    int nT = blockIdx.y;
    int n0 = nT * 128;

    int t = threadIdx.x;
    MmaCtx cx;
    cx.sbase = sbase;
    cx.lane = t & 31;
    int w = t >> 5;
    cx.wm = w >> 2; cx.wn = w & 3;

    const uint32_t* aSrc = g_hP  + (((size_t)e * MT_N + mT) * KI2) * 4096;
    const uint32_t* bSrc = g_woP + (((size_t)e * NT2 + nT) * KI2) * 4096;

    float acc[4][4][4];
#pragma unroll
    for (int a = 0; a < 4; a++)
#pragma unroll
        for (int b = 0; b < 4; b++)
#pragma unroll
            for (int c = 0; c < 4; c++) acc[a][b][c] = 0.f;

    gemm_mainloop<KI2>(cx, mbb, aSrc, bSrc, t, acc);

    // epilogue: weight * acc scattered to out rows (register-only, no smem)
    int ln = cx.lane;
    int rr = ln >> 2, bb = ln & 3;
    int m0 = mT * 128;
#pragma unroll
    for (int mt = 0; mt < 4; mt++) {
#pragma unroll
        for (int h = 0; h < 2; h++) {
            int m = m0 + cx.wm * 64 + mt * 16 + rr + 8 * h;
            int tok = g_token_of_slot[e * CAP + m];
            if (tok < 0) continue;
            float wgt = g_slot_wt[e * CAP + m];
            float* orow = outp + (size_t)tok * H_DIM + n0 + cx.wn * 32;
#pragma unroll
            for (int nt = 0; nt < 4; nt++) {
                float2 v;
                v.x = wgt * acc[mt][nt][2 * h];
                v.y = wgt * acc[mt][nt][2 * h + 1];
                *(float2*)&orow[nt * 8 + 2 * bb] = v;
            }
        }
    }
}

extern "C" void kernel_launch(void* const* d_in, const int* in_sizes, int n_in,
                              void* d_out, int out_size) {
    const float* tokens = (const float*)d_in[0];
    const float* gw     = (const float*)d_in[1];
    const float* wi     = (const float*)d_in[2];
    const float* wo     = (const float*)d_in[3];
    float* outp = (float*)d_out;

    const int SMEM = 3 * STG_B;   // 98304 -> 2 CTA/SM
    cudaFuncSetAttribute(gemm1_tc, cudaFuncAttributeMaxDynamicSharedMemorySize, SMEM);
    cudaFuncSetAttribute(gemm2_tc, cudaFuncAttributeMaxDynamicSharedMemorySize, SMEM);

    prep_wi_gate<<<PWI_BLKS + GATE_BLKS + ZERO_BLKS, 256>>>(tokens, gw, wi, outp); // 1
    rank_kernel<<<1, 1024>>>();                                                    // 2
    dispatch_aP<<<dim3(KI1, MT_N, N_EXP), 256>>>(tokens);                          // 3
    gemm1_tc<<<dim3(MT_N, NT1, N_EXP), 256, SMEM>>>(nullptr);                      // 4
    prep_wo<<<dim3(NT2, KI2, N_EXP), 256>>>(wo);                                   // 5
    gemm2_tc<<<dim3(MT_N, NT2, N_EXP), 256, SMEM>>>(outp);                         // 6
}

// round 15
// speedup vs baseline: 1.3885x; 1.3885x over previous
#include <cuda_runtime.h>
#include <cuda_bf16.h>
#include <cstdint>

// Problem shapes (fixed by setup_inputs)
constexpr int T_TOK = 8192;
constexpr int H_DIM = 2048;
constexpr int I_DIM = 8192;
constexpr int N_EXP = 8;
constexpr int CAP   = 1280;

constexpr int MT_N  = CAP / 128;      // 10 m-tiles per expert
constexpr int KI1   = H_DIM / 32;     // 64  k-iters gemm1
constexpr int KI2   = I_DIM / 32;     // 256 k-iters gemm2
constexpr int KH2   = KI2 / 2;        // 128 k-iters per split-K half
constexpr int NT1   = I_DIM / 128;    // 64  n-tiles gemm1
constexpr int NT2   = H_DIM / 128;    // 16  n-tiles gemm2

constexpr int PWI_BLKS  = NT1 * KI1 * N_EXP;    // 32768 prep_wi CTAs
constexpr int GATE_BLKS = T_TOK / 8;            // 1024
constexpr int ZERO_BLKS = 1024;                 // zero d_out

// ---------------------------------------------------------------------------
// Device-global scratch (fragment-permuted tf32 operand tiles)
// tile = 4096 u32 = one 128(rows) x 32(k) A-tile or 32(k) x 128(n) B-tile
// NOTE: device-code references only (host-side use binds the host shadow).
// ---------------------------------------------------------------------------
__device__ uint32_t g_wiP[(size_t)N_EXP * NT1 * KI1 * 4096];  // 512MiB
__device__ uint32_t g_woP[(size_t)N_EXP * NT2 * KI2 * 4096];  // 512MiB
__device__ uint32_t g_aP [(size_t)N_EXP * MT_N * KI1 * 4096]; //  80MiB
__device__ uint32_t g_hP [(size_t)N_EXP * MT_N * KI2 * 4096]; // 320MiB
__device__ int   g_top1[T_TOK];
__device__ float g_wt[T_TOK];
__device__ int   g_token_of_slot[N_EXP * CAP];
__device__ float g_slot_wt[N_EXP * CAP];
__device__ int   g_counts[N_EXP];

// ---------------------------------------------------------------------------
// helpers
// ---------------------------------------------------------------------------
__device__ __forceinline__ uint32_t f2tf32(float f) {
    uint32_t u;
    asm("cvt.rna.tf32.f32 %0, %1;" : "=r"(u) : "f"(f));
    return u;
}
__device__ __forceinline__ void mma_tf32(float* c,
                                         uint32_t a0, uint32_t a1, uint32_t a2, uint32_t a3,
                                         uint32_t b0, uint32_t b1) {
    asm volatile(
        "mma.sync.aligned.m16n8k8.row.col.f32.tf32.tf32.f32 "
        "{%0,%1,%2,%3}, {%4,%5,%6,%7}, {%8,%9}, {%0,%1,%2,%3};"
        : "+f"(c[0]), "+f"(c[1]), "+f"(c[2]), "+f"(c[3])
        : "r"(a0), "r"(a1), "r"(a2), "r"(a3), "r"(b0), "r"(b1));
}
__device__ __forceinline__ uint32_t smem_u32(const void* p) {
    uint32_t a;
    asm("{ .reg .u64 t; cvta.to.shared.u64 t, %1; cvt.u32.u64 %0, t; }"
        : "=r"(a) : "l"(p));
    return a;
}
__device__ __forceinline__ void mbar_init(uint32_t a, uint32_t cnt) {
    asm volatile("mbarrier.init.shared.b64 [%0], %1;" :: "r"(a), "r"(cnt) : "memory");
}
__device__ __forceinline__ void mbar_expect(uint32_t a, uint32_t tx) {
    asm volatile("mbarrier.arrive.expect_tx.shared.b64 _, [%0], %1;"
                 :: "r"(a), "r"(tx) : "memory");
}
__device__ __forceinline__ void mbar_arrive(uint32_t a) {
    asm volatile("mbarrier.arrive.shared.b64 _, [%0];" :: "r"(a) : "memory");
}
__device__ __forceinline__ void bulk_g2s(uint32_t dst, const void* src,
                                         uint32_t bytes, uint32_t mbar) {
    asm volatile(
        "cp.async.bulk.shared::cta.global.mbarrier::complete_tx::bytes "
        "[%0], [%1], %2, [%3];"
        :: "r"(dst), "l"(src), "r"(bytes), "r"(mbar) : "memory");
}
__device__ __forceinline__ void mbar_wait(uint32_t a, uint32_t ph) {
    asm volatile(
        "{\n\t.reg .pred P;\n\t"
        "W%=:\n\t"
        "mbarrier.try_wait.parity.shared.b64 P, [%0], %1;\n\t"
        "@!P bra W%=;\n\t}"
        :: "r"(a), "r"(ph) : "memory");
}
__device__ __forceinline__ float gelu_exact(float x) {
    return 0.5f * x * (1.f + erff(x * 0.7071067811865475f));
}

// shared permute body: ts is [32][136] floats in smem, dst is one 4096-u32 tile
__device__ __forceinline__ void permute_store(const float* ts, uint32_t* d, int t) {
#pragma unroll
    for (int j = 0; j < 8; j++) {
        int q  = t + 256 * j;
        int ln = q & 31;
        int g  = q >> 5;
        int nt = g & 15, kk = g >> 4;
        int n  = nt * 8 + (ln >> 2);
        int k  = kk * 8 + (ln & 3);
        uint2 v;
        v.x = f2tf32(ts[k * 136 + n]);
        v.y = f2tf32(ts[(k + 4) * 136 + n]);
        *(uint2*)(d + (size_t)q * 2) = v;
    }
}

// ---------------------------------------------------------------------------
// Launch 1: fused prep_wi + gating + zero(d_out)
// ---------------------------------------------------------------------------
__global__ __launch_bounds__(256)
void prep_wi_gate(const float* __restrict__ tokens,
                  const float* __restrict__ gw,
                  const float* __restrict__ wi,
                  float* __restrict__ outp) {
    __shared__ float ts[32 * 136];
    int bid = blockIdx.x;
    int t = threadIdx.x;
    if (bid < PWI_BLKS) {
        int e = bid >> 12;
        int rem = bid & 4095;
        int bx = rem >> 6;
        int by = rem & 63;
        int n0 = bx * 128, k0 = by * 32;
        const float* s = wi + ((size_t)e * H_DIM + k0) * I_DIM + n0;
#pragma unroll
        for (int i = 0; i < 16; i++) {
            int f = t + 256 * i;
            int r = f >> 7, c = f & 127;
            ts[r * 136 + c] = s[(size_t)r * I_DIM + c];
        }
        __syncthreads();
        uint32_t* d = g_wiP + (((size_t)e * 64 + bx) * 64 + by) * 4096;
        permute_store(ts, d, t);
    } else if (bid < PWI_BLKS + GATE_BLKS) {
        int warp = t >> 5;
        int lane = t & 31;
        int tok = (bid - PWI_BLKS) * 8 + warp;
        if (tok >= T_TOK) return;
        const float* x = tokens + (size_t)tok * H_DIM;
        float acc[N_EXP];
#pragma unroll
        for (int e = 0; e < N_EXP; e++) acc[e] = 0.f;
        for (int k = lane; k < H_DIM; k += 32) {
            float xv = x[k];
#pragma unroll
            for (int e = 0; e < N_EXP; e++)
                acc[e] = fmaf(xv, gw[e * H_DIM + k], acc[e]);
        }
#pragma unroll
        for (int off = 16; off; off >>= 1)
#pragma unroll
            for (int e = 0; e < N_EXP; e++)
                acc[e] += __shfl_xor_sync(0xffffffffu, acc[e], off);
        if (lane == 0) {
            int best = 0; float bv = acc[0];
#pragma unroll
            for (int e = 1; e < N_EXP; e++)
                if (acc[e] > bv) { bv = acc[e]; best = e; }
            float s = 0.f;
#pragma unroll
            for (int e = 0; e < N_EXP; e++) s += expf(acc[e] - bv);
            g_top1[tok] = best;
            g_wt[tok]   = 1.f / s;
        }
    } else {
        int zb = bid - (PWI_BLKS + GATE_BLKS);
        float4* dst = (float4*)outp + (size_t)zb * 4096 + t;
        float4 z = make_float4(0.f, 0.f, 0.f, 0.f);
#pragma unroll
        for (int i = 0; i < 16; i++) dst[i * 256] = z;
    }
}

// ---------------------------------------------------------------------------
// Launch 2: rank_kernel (verified)
// ---------------------------------------------------------------------------
__global__ void rank_kernel() {
    __shared__ int sc[1024][N_EXP];
    int tid = threadIdx.x;
    for (int s = tid; s < N_EXP * CAP; s += 1024) g_token_of_slot[s] = -1;
    int el[8], cnt[N_EXP];
#pragma unroll
    for (int e = 0; e < N_EXP; e++) cnt[e] = 0;
#pragma unroll
    for (int i = 0; i < 8; i++) {
        int t = tid * 8 + i;
        int e = g_top1[t];
        el[i] = e; cnt[e]++;
    }
#pragma unroll
    for (int e = 0; e < N_EXP; e++) sc[tid][e] = cnt[e];
    __syncthreads();
    for (int off = 1; off < 1024; off <<= 1) {
        int v[N_EXP];
        if (tid >= off)
#pragma unroll
            for (int e = 0; e < N_EXP; e++) v[e] = sc[tid - off][e];
        __syncthreads();
        if (tid >= off)
#pragma unroll
            for (int e = 0; e < N_EXP; e++) sc[tid][e] += v[e];
        __syncthreads();
    }
    int base[N_EXP];
#pragma unroll
    for (int e = 0; e < N_EXP; e++) base[e] = sc[tid][e] - cnt[e];
#pragma unroll
    for (int i = 0; i < 8; i++) {
        int t = tid * 8 + i;
        int e = el[i];
        int r = base[e]++;
        if (r < CAP) {
            g_token_of_slot[e * CAP + r] = t;
            g_slot_wt[e * CAP + r]       = g_wt[t];
        }
    }
    if (tid == 1023)
#pragma unroll
        for (int e = 0; e < N_EXP; e++) g_counts[e] = min(sc[1023][e], CAP);
}

// ---------------------------------------------------------------------------
// Launch 3: dispatch_aP (verified)
// ---------------------------------------------------------------------------
__global__ __launch_bounds__(256)
void dispatch_aP(const float* __restrict__ tokens) {
    __shared__ float ts[128][36];
    int e = blockIdx.z, mT = blockIdx.y, kI = blockIdx.x;
    int k0 = kI * 32;
    int t = threadIdx.x;
#pragma unroll
    for (int i = 0; i < 4; i++) {
        int f = t + 256 * i;
        int row = f >> 3, c4 = (f & 7) * 4;
        int tok = g_token_of_slot[e * CAP + mT * 128 + row];
        float4 v = (tok >= 0)
                 ? *(const float4*)(tokens + (size_t)tok * H_DIM + k0 + c4)
                 : make_float4(0.f, 0.f, 0.f, 0.f);
        *(float4*)&ts[row][c4] = v;
    }
    __syncthreads();
    uint32_t* d = g_aP + (((size_t)e * MT_N + mT) * KI1 + kI) * 4096;
    int ln = t & 31, mt = t >> 5;
    int r = ln >> 2, b = ln & 3;
#pragma unroll
    for (int j = 0; j < 4; j++) {
        int row = mt * 16 + r;
        int k = j * 8 + b;
        uint4 v;
        v.x = f2tf32(ts[row][k]);
        v.y = f2tf32(ts[row + 8][k]);
        v.z = f2tf32(ts[row][k + 4]);
        v.w = f2tf32(ts[row + 8][k + 4]);
        *(uint4*)(d + (size_t)(t + 256 * j) * 4) = v;
    }
}

// ---------------------------------------------------------------------------
// Launch 5: prep_wo (standalone, high occupancy)
// ---------------------------------------------------------------------------
__global__ __launch_bounds__(256)
void prep_wo(const float* __restrict__ wo) {
    __shared__ float ts[32 * 136];
    int e = blockIdx.z;
    int n0 = blockIdx.x * 128, k0 = blockIdx.y * 32;
    const float* s = wo + ((size_t)e * I_DIM + k0) * H_DIM + n0;
    int t = threadIdx.x;
#pragma unroll
    for (int i = 0; i < 16; i++) {
        int f = t + 256 * i;
        int r = f >> 7, c = f & 127;
        ts[r * 136 + c] = s[(size_t)r * H_DIM + c];
    }
    __syncthreads();
    uint32_t* d = g_woP + (((size_t)e * NT2 + blockIdx.x) * KI2 + blockIdx.y) * 4096;
    permute_store(ts, d, t);
}

// ---------------------------------------------------------------------------
// GEMM core: 128x128x32 tf32, 3-stage TMA-bulk pipeline, full/empty mbarriers,
// rotating refill warp, A-fragment double buffering. 96KB -> 2 CTA/SM.
// mbs: full[s] at +8s; empty[s] at +24+8s.
// ---------------------------------------------------------------------------
#define STG_B 32768

struct MmaCtx {
    uint32_t sbase;
    int lane, wm, wn;
};

__device__ __forceinline__ void ld_a4(uint4* af, uint32_t aB, int kk,
                                      int wm, int lane) {
#pragma unroll
    for (int mt = 0; mt < 4; mt++) {
        uint32_t addr = aB + (((kk * 8 + wm * 4 + mt) * 32 + lane) << 4);
        asm volatile("ld.shared.v4.b32 {%0,%1,%2,%3}, [%4];"
                     : "=r"(af[mt].x), "=r"(af[mt].y),
                       "=r"(af[mt].z), "=r"(af[mt].w) : "r"(addr));
    }
}

__device__ __forceinline__ void consume_stage(const MmaCtx& cx, int s,
                                              float acc[4][4][4]) {
    uint32_t aB = cx.sbase + s * STG_B;
    uint32_t bB = aB + 16384;
    uint4 af[2][4];
    ld_a4(af[0], aB, 0, cx.wm, cx.lane);
#pragma unroll
    for (int kk = 0; kk < 4; kk++) {
        int cur = kk & 1;
        uint2 bf[4];
#pragma unroll
        for (int nt = 0; nt < 4; nt++) {
            uint32_t addr = bB + (((kk * 16 + cx.wn * 4 + nt) * 32 + cx.lane) << 3);
            asm volatile("ld.shared.v2.b32 {%0,%1}, [%2];"
                         : "=r"(bf[nt].x), "=r"(bf[nt].y) : "r"(addr));
        }
        if (kk < 3) ld_a4(af[cur ^ 1], aB, kk + 1, cx.wm, cx.lane);
#pragma unroll
        for (int mt = 0; mt < 4; mt++)
#pragma unroll
            for (int nt = 0; nt < 4; nt++)
                mma_tf32(acc[mt][nt], af[cur][mt].x, af[cur][mt].y,
                         af[cur][mt].z, af[cur][mt].w, bf[nt].x, bf[nt].y);
    }
}

// refill stage s with k-iter `it` tiles via 2 bulk copies (single thread)
__device__ __forceinline__ void fill_stage(uint32_t sbase, uint32_t mbar_base,
                                           int s, const uint32_t* aSrc,
                                           const uint32_t* bSrc, int it) {
    uint32_t mb = mbar_base + s * 8;
    uint32_t st = sbase + s * STG_B;
    mbar_expect(mb, 32768);
    bulk_g2s(st,         aSrc + (size_t)it * 4096, 16384, mb);
    bulk_g2s(st + 16384, bSrc + (size_t)it * 4096, 16384, mb);
}

// shared mainloop: full/empty mbarrier pipeline, refill warp rotates (it&7)
template <int KI>
__device__ __forceinline__ void gemm_mainloop(const MmaCtx& cx, uint32_t mbb,
                                              const uint32_t* aSrc,
                                              const uint32_t* bSrc,
                                              int t, float acc[4][4][4]) {
    if (t == 0) {
#pragma unroll
        for (int s = 0; s < 3; s++) {
            mbar_init(mbb + s * 8, 1);        // full: tx-based
            mbar_init(mbb + 24 + s * 8, 8);   // empty: 8 warp arrivals
        }
    }
    __syncthreads();
    if (t == 0) {
#pragma unroll
        for (int p = 0; p < 3; p++) fill_stage(cx.sbase, mbb, p, aSrc, bSrc, p);
    }
    int w = t >> 5;
    for (int it = 0; it < KI; ++it) {
        int s = it % 3;
        uint32_t ph = (uint32_t)((it / 3) & 1);
        mbar_wait(mbb + s * 8, ph);
        consume_stage(cx, s, acc);
        if (cx.lane == 0) mbar_arrive(mbb + 24 + s * 8);
        if (it + 3 < KI && w == (it & 7) && cx.lane == 0) {
            mbar_wait(mbb + 24 + s * 8, ph);      // all 8 warps drained stage s
            fill_stage(cx.sbase, mbb, s, aSrc, bSrc, it + 3);
        }
    }
}

// ---------------------------------------------------------------------------
// Launch 4 (ncu slot): GEMM1: g_aP @ g_wiP -> gelu -> g_hP. mT fastest.
// ---------------------------------------------------------------------------
__global__ __launch_bounds__(256, 2)
void gemm1_tc(float* dummy) {
    extern __shared__ char smem[];
    __shared__ __align__(8) uint64_t mbs[6];
    uint32_t sbase = smem_u32(smem);
    uint32_t mbb   = smem_u32(mbs);

    int e = blockIdx.z;
    int cnt = g_counts[e];
    int mT = blockIdx.x;
    if (mT * 128 >= cnt) return;
    int nT = blockIdx.y;

    int t = threadIdx.x;
    MmaCtx cx;
    cx.sbase = sbase;
    cx.lane = t & 31;
    int w = t >> 5;
    cx.wm = w >> 2; cx.wn = w & 3;

    const uint32_t* aSrc = g_aP  + (((size_t)e * MT_N + mT) * KI1) * 4096;
    const uint32_t* bSrc = g_wiP + (((size_t)e * NT1 + nT) * KI1) * 4096;

    float acc[4][4][4];
#pragma unroll
    for (int a = 0; a < 4; a++)
#pragma unroll
        for (int b = 0; b < 4; b++)
#pragma unroll
            for (int c = 0; c < 4; c++) acc[a][b][c] = 0.f;

    gemm_mainloop<KI1>(cx, mbb, aSrc, bSrc, t, acc);
    __syncthreads();   // all warps done with all stages before smem reuse

    // epilogue: gelu -> fragment-permuted g_hP via smem bounce (128x68 f32)
    float* eb = (float*)smem;
    int ln = cx.lane;
    int rr = ln >> 2, bb = ln & 3;
#pragma unroll
    for (int half = 0; half < 2; half++) {
        if ((cx.wn >> 1) == half) {
            int colbase = (cx.wn & 1) * 32;
#pragma unroll
            for (int mt = 0; mt < 4; mt++) {
                int row = cx.wm * 64 + mt * 16 + rr;
#pragma unroll
                for (int nt = 0; nt < 4; nt++) {
                    int col = colbase + nt * 8 + 2 * bb;
                    float2 v0, v1;
                    v0.x = gelu_exact(acc[mt][nt][0]);
                    v0.y = gelu_exact(acc[mt][nt][1]);
                    v1.x = gelu_exact(acc[mt][nt][2]);
                    v1.y = gelu_exact(acc[mt][nt][3]);
                    *(float2*)&eb[row * 68 + col]       = v0;
                    *(float2*)&eb[(row + 8) * 68 + col] = v1;
                }
            }
        }
        __syncthreads();
        int mt8 = t >> 5;
#pragma unroll
        for (int kl = 0; kl < 2; kl++) {
            int kI = nT * 4 + half * 2 + kl;
            uint32_t* d = g_hP + (((size_t)e * MT_N + mT) * KI2 + kI) * 4096;
#pragma unroll
            for (int j = 0; j < 4; j++) {   // j = kk
                int row = mt8 * 16 + rr;
                int c = kl * 32 + j * 8 + bb;
                uint4 v;
                v.x = f2tf32(eb[row * 68 + c]);
                v.y = f2tf32(eb[(row + 8) * 68 + c]);
                v.z = f2tf32(eb[row * 68 + c + 4]);
                v.w = f2tf32(eb[(row + 8) * 68 + c + 4]);
                *(uint4*)(d + (size_t)(t + 256 * j) * 4) = v;
            }
        }
        __syncthreads();
    }
}

// ---------------------------------------------------------------------------
// Launch 6: GEMM2 split-K(2): g_hP @ g_woP -> weight-scaled atomicAdd to out.
// grid (MT_N, NT2, 2*N_EXP): z = 2e+kh; each half does 128 k-iters.
// Each output element receives exactly 2 float atomics (commutative -> det.)
// ---------------------------------------------------------------------------
__global__ __launch_bounds__(256, 2)
void gemm2_tc(float* __restrict__ outp) {
    extern __shared__ char smem[];
    __shared__ __align__(8) uint64_t mbs[6];
    uint32_t sbase = smem_u32(smem);
    uint32_t mbb   = smem_u32(mbs);

    int ez = blockIdx.z;
    int e  = ez >> 1;
    int kh = ez & 1;
    int cnt = g_counts[e];
    int mT = blockIdx.x;
    if (mT * 128 >= cnt) return;
    int nT = blockIdx.y;
    int n0 = nT * 128;

    int t = threadIdx.x;
    MmaCtx cx;
    cx.sbase = sbase;
    cx.lane = t & 31;
    int w = t >> 5;
    cx.wm = w >> 2; cx.wn = w & 3;

    const uint32_t* aSrc = g_hP + (((size_t)e * MT_N + mT) * KI2
                                   + (size_t)kh * KH2) * 4096;
    const uint32_t* bSrc = g_woP + (((size_t)e * NT2 + nT) * KI2
                                    + (size_t)kh * KH2) * 4096;

    float acc[4][4][4];
#pragma unroll
    for (int a = 0; a < 4; a++)
#pragma unroll
        for (int b = 0; b < 4; b++)
#pragma unroll
            for (int c = 0; c < 4; c++) acc[a][b][c] = 0.f;

    gemm_mainloop<KH2>(cx, mbb, aSrc, bSrc, t, acc);

    // epilogue: weight * acc atomically accumulated into out rows
    int ln = cx.lane;
    int rr = ln >> 2, bb = ln & 3;
    int m0 = mT * 128;
#pragma unroll
    for (int mt = 0; mt < 4; mt++) {
#pragma unroll
        for (int h = 0; h < 2; h++) {
            int m = m0 + cx.wm * 64 + mt * 16 + rr + 8 * h;
            int tok = g_token_of_slot[e * CAP + m];
            if (tok < 0) continue;
            float wgt = g_slot_wt[e * CAP + m];
            float* orow = outp + (size_t)tok * H_DIM + n0 + cx.wn * 32;
#pragma unroll
            for (int nt = 0; nt < 4; nt++) {
                atomicAdd(&orow[nt * 8 + 2 * bb],     wgt * acc[mt][nt][2 * h]);
                atomicAdd(&orow[nt * 8 + 2 * bb + 1], wgt * acc[mt][nt][2 * h + 1]);
            }
        }
    }
}

extern "C" void kernel_launch(void* const* d_in, const int* in_sizes, int n_in,
                              void* d_out, int out_size) {
    const float* tokens = (const float*)d_in[0];
    const float* gw     = (const float*)d_in[1];
    const float* wi     = (const float*)d_in[2];
    const float* wo     = (const float*)d_in[3];
    float* outp = (float*)d_out;

    const int SMEM = 3 * STG_B;   // 98304 -> 2 CTA/SM
    cudaFuncSetAttribute(gemm1_tc, cudaFuncAttributeMaxDynamicSharedMemorySize, SMEM);
    cudaFuncSetAttribute(gemm2_tc, cudaFuncAttributeMaxDynamicSharedMemorySize, SMEM);

    prep_wi_gate<<<PWI_BLKS + GATE_BLKS + ZERO_BLKS, 256>>>(tokens, gw, wi, outp); // 1
    rank_kernel<<<1, 1024>>>();                                                    // 2
    dispatch_aP<<<dim3(KI1, MT_N, N_EXP), 256>>>(tokens);                          // 3
    gemm1_tc<<<dim3(MT_N, NT1, N_EXP), 256, SMEM>>>(nullptr);                      // 4
    prep_wo<<<dim3(NT2, KI2, N_EXP), 256>>>(wo);                                   // 5
    gemm2_tc<<<dim3(MT_N, NT2, 2 * N_EXP), 256, SMEM>>>(outp);                     // 6
}

// round 16
// speedup vs baseline: 1.4070x; 1.0134x over previous
#include <cuda_runtime.h>
#include <cuda_bf16.h>
#include <cstdint>

// Problem shapes (fixed by setup_inputs)
constexpr int T_TOK = 8192;
constexpr int H_DIM = 2048;
constexpr int I_DIM = 8192;
constexpr int N_EXP = 8;
constexpr int CAP   = 1280;

constexpr int MT_N  = CAP / 128;      // 10 m-tiles per expert
constexpr int KI1   = H_DIM / 32;     // 64  k-iters gemm1
constexpr int KI2   = I_DIM / 32;     // 256 k-iters gemm2
constexpr int KH2   = KI2 / 2;        // 128 k-iters per split-K half
constexpr int NT1   = I_DIM / 128;    // 64  n-tiles gemm1
constexpr int NT2   = H_DIM / 128;    // 16  n-tiles gemm2

constexpr int PWI_BLKS  = NT1 * KI1 * N_EXP;    // 32768 prep_wi CTAs
constexpr int GATE_BLKS = T_TOK / 8;            // 1024
constexpr int ZERO_BLKS = 1024;                 // zero d_out

// ---------------------------------------------------------------------------
// Device-global scratch (fragment-permuted tf32 operand tiles)
// tile = 4096 u32 = one 128(rows) x 32(k) A-tile or 32(k) x 128(n) B-tile
// NOTE: device-code references only (host-side use binds the host shadow).
// ---------------------------------------------------------------------------
__device__ uint32_t g_wiP[(size_t)N_EXP * NT1 * KI1 * 4096];  // 512MiB
__device__ uint32_t g_woP[(size_t)N_EXP * NT2 * KI2 * 4096];  // 512MiB
__device__ uint32_t g_aP [(size_t)N_EXP * MT_N * KI1 * 4096]; //  80MiB
__device__ uint32_t g_hP [(size_t)N_EXP * MT_N * KI2 * 4096]; // 320MiB
__device__ int   g_top1[T_TOK];
__device__ float g_wt[T_TOK];
__device__ int   g_token_of_slot[N_EXP * CAP];
__device__ float g_slot_wt[N_EXP * CAP];
__device__ int   g_counts[N_EXP];

// ---------------------------------------------------------------------------
// helpers
// ---------------------------------------------------------------------------
__device__ __forceinline__ uint32_t f2tf32(float f) {
    uint32_t u;
    asm("cvt.rna.tf32.f32 %0, %1;" : "=r"(u) : "f"(f));
    return u;
}
__device__ __forceinline__ void mma_tf32(float* c,
                                         uint32_t a0, uint32_t a1, uint32_t a2, uint32_t a3,
                                         uint32_t b0, uint32_t b1) {
    asm volatile(
        "mma.sync.aligned.m16n8k8.row.col.f32.tf32.tf32.f32 "
        "{%0,%1,%2,%3}, {%4,%5,%6,%7}, {%8,%9}, {%0,%1,%2,%3};"
        : "+f"(c[0]), "+f"(c[1]), "+f"(c[2]), "+f"(c[3])
        : "r"(a0), "r"(a1), "r"(a2), "r"(a3), "r"(b0), "r"(b1));
}
__device__ __forceinline__ uint32_t smem_u32(const void* p) {
    uint32_t a;
    asm("{ .reg .u64 t; cvta.to.shared.u64 t, %1; cvt.u32.u64 %0, t; }"
        : "=r"(a) : "l"(p));
    return a;
}
__device__ __forceinline__ void mbar_init(uint32_t a, uint32_t cnt) {
    asm volatile("mbarrier.init.shared.b64 [%0], %1;" :: "r"(a), "r"(cnt) : "memory");
}
__device__ __forceinline__ void mbar_expect(uint32_t a, uint32_t tx) {
    asm volatile("mbarrier.arrive.expect_tx.shared.b64 _, [%0], %1;"
                 :: "r"(a), "r"(tx) : "memory");
}
__device__ __forceinline__ void mbar_arrive(uint32_t a) {
    asm volatile("mbarrier.arrive.shared.b64 _, [%0];" :: "r"(a) : "memory");
}
__device__ __forceinline__ void bulk_g2s(uint32_t dst, const void* src,
                                         uint32_t bytes, uint32_t mbar) {
    asm volatile(
        "cp.async.bulk.shared::cta.global.mbarrier::complete_tx::bytes "
        "[%0], [%1], %2, [%3];"
        :: "r"(dst), "l"(src), "r"(bytes), "r"(mbar) : "memory");
}
__device__ __forceinline__ void mbar_wait(uint32_t a, uint32_t ph) {
    asm volatile(
        "{\n\t.reg .pred P;\n\t"
        "W%=:\n\t"
        "mbarrier.try_wait.parity.shared.b64 P, [%0], %1;\n\t"
        "@!P bra W%=;\n\t}"
        :: "r"(a), "r"(ph) : "memory");
}
__device__ __forceinline__ float gelu_exact(float x) {
    return 0.5f * x * (1.f + erff(x * 0.7071067811865475f));
}

// shared permute body: ts is [32][136] floats in smem, dst is one 4096-u32 tile
__device__ __forceinline__ void permute_store(const float* ts, uint32_t* d, int t) {
#pragma unroll
    for (int j = 0; j < 8; j++) {
        int q  = t + 256 * j;
        int ln = q & 31;
        int g  = q >> 5;
        int nt = g & 15, kk = g >> 4;
        int n  = nt * 8 + (ln >> 2);
        int k  = kk * 8 + (ln & 3);
        uint2 v;
        v.x = f2tf32(ts[k * 136 + n]);
        v.y = f2tf32(ts[(k + 4) * 136 + n]);
        *(uint2*)(d + (size_t)q * 2) = v;
    }
}

// ---------------------------------------------------------------------------
// Launch 1: fused prep_wi + gating + zero(d_out)
// ---------------------------------------------------------------------------
__global__ __launch_bounds__(256)
void prep_wi_gate(const float* __restrict__ tokens,
                  const float* __restrict__ gw,
                  const float* __restrict__ wi,
                  float* __restrict__ outp) {
    __shared__ float ts[32 * 136];
    int bid = blockIdx.x;
    int t = threadIdx.x;
    if (bid < PWI_BLKS) {
        int e = bid >> 12;
        int rem = bid & 4095;
        int bx = rem >> 6;
        int by = rem & 63;
        int n0 = bx * 128, k0 = by * 32;
        const float* s = wi + ((size_t)e * H_DIM + k0) * I_DIM + n0;
#pragma unroll
        for (int i = 0; i < 16; i++) {
            int f = t + 256 * i;
            int r = f >> 7, c = f & 127;
            ts[r * 136 + c] = s[(size_t)r * I_DIM + c];
        }
        __syncthreads();
        uint32_t* d = g_wiP + (((size_t)e * 64 + bx) * 64 + by) * 4096;
        permute_store(ts, d, t);
    } else if (bid < PWI_BLKS + GATE_BLKS) {
        int warp = t >> 5;
        int lane = t & 31;
        int tok = (bid - PWI_BLKS) * 8 + warp;
        if (tok >= T_TOK) return;
        const float* x = tokens + (size_t)tok * H_DIM;
        float acc[N_EXP];
#pragma unroll
        for (int e = 0; e < N_EXP; e++) acc[e] = 0.f;
        for (int k = lane; k < H_DIM; k += 32) {
            float xv = x[k];
#pragma unroll
            for (int e = 0; e < N_EXP; e++)
                acc[e] = fmaf(xv, gw[e * H_DIM + k], acc[e]);
        }
#pragma unroll
        for (int off = 16; off; off >>= 1)
#pragma unroll
            for (int e = 0; e < N_EXP; e++)
                acc[e] += __shfl_xor_sync(0xffffffffu, acc[e], off);
        if (lane == 0) {
            int best = 0; float bv = acc[0];
#pragma unroll
            for (int e = 1; e < N_EXP; e++)
                if (acc[e] > bv) { bv = acc[e]; best = e; }
            float s = 0.f;
#pragma unroll
            for (int e = 0; e < N_EXP; e++) s += expf(acc[e] - bv);
            g_top1[tok] = best;
            g_wt[tok]   = 1.f / s;
        }
    } else {
        int zb = bid - (PWI_BLKS + GATE_BLKS);
        float4* dst = (float4*)outp + (size_t)zb * 4096 + t;
        float4 z = make_float4(0.f, 0.f, 0.f, 0.f);
#pragma unroll
        for (int i = 0; i < 16; i++) dst[i * 256] = z;
    }
}

// ---------------------------------------------------------------------------
// Launch 2: rank_kernel (verified)
// ---------------------------------------------------------------------------
__global__ void rank_kernel() {
    __shared__ int sc[1024][N_EXP];
    int tid = threadIdx.x;
    for (int s = tid; s < N_EXP * CAP; s += 1024) g_token_of_slot[s] = -1;
    int el[8], cnt[N_EXP];
#pragma unroll
    for (int e = 0; e < N_EXP; e++) cnt[e] = 0;
#pragma unroll
    for (int i = 0; i < 8; i++) {
        int t = tid * 8 + i;
        int e = g_top1[t];
        el[i] = e; cnt[e]++;
    }
#pragma unroll
    for (int e = 0; e < N_EXP; e++) sc[tid][e] = cnt[e];
    __syncthreads();
    for (int off = 1; off < 1024; off <<= 1) {
        int v[N_EXP];
        if (tid >= off)
#pragma unroll
            for (int e = 0; e < N_EXP; e++) v[e] = sc[tid - off][e];
        __syncthreads();
        if (tid >= off)
#pragma unroll
            for (int e = 0; e < N_EXP; e++) sc[tid][e] += v[e];
        __syncthreads();
    }
    int base[N_EXP];
#pragma unroll
    for (int e = 0; e < N_EXP; e++) base[e] = sc[tid][e] - cnt[e];
#pragma unroll
    for (int i = 0; i < 8; i++) {
        int t = tid * 8 + i;
        int e = el[i];
        int r = base[e]++;
        if (r < CAP) {
            g_token_of_slot[e * CAP + r] = t;
            g_slot_wt[e * CAP + r]       = g_wt[t];
        }
    }
    if (tid == 1023)
#pragma unroll
        for (int e = 0; e < N_EXP; e++) g_counts[e] = min(sc[1023][e], CAP);
}

// ---------------------------------------------------------------------------
// Launch 3: dispatch_aP (verified)
// ---------------------------------------------------------------------------
__global__ __launch_bounds__(256)
void dispatch_aP(const float* __restrict__ tokens) {
    __shared__ float ts[128][36];
    int e = blockIdx.z, mT = blockIdx.y, kI = blockIdx.x;
    int k0 = kI * 32;
    int t = threadIdx.x;
#pragma unroll
    for (int i = 0; i < 4; i++) {
        int f = t + 256 * i;
        int row = f >> 3, c4 = (f & 7) * 4;
        int tok = g_token_of_slot[e * CAP + mT * 128 + row];
        float4 v = (tok >= 0)
                 ? *(const float4*)(tokens + (size_t)tok * H_DIM + k0 + c4)
                 : make_float4(0.f, 0.f, 0.f, 0.f);
        *(float4*)&ts[row][c4] = v;
    }
    __syncthreads();
    uint32_t* d = g_aP + (((size_t)e * MT_N + mT) * KI1 + kI) * 4096;
    int ln = t & 31, mt = t >> 5;
    int r = ln >> 2, b = ln & 3;
#pragma unroll
    for (int j = 0; j < 4; j++) {
        int row = mt * 16 + r;
        int k = j * 8 + b;
        uint4 v;
        v.x = f2tf32(ts[row][k]);
        v.y = f2tf32(ts[row + 8][k]);
        v.z = f2tf32(ts[row][k + 4]);
        v.w = f2tf32(ts[row + 8][k + 4]);
        *(uint4*)(d + (size_t)(t + 256 * j) * 4) = v;
    }
}

// ---------------------------------------------------------------------------
// Launch 5: prep_wo — launched with ProgrammaticStreamSerialization so it
// overlaps gemm1's tail (no data dependency on gemm1; DRAM-bound vs tensor).
// ---------------------------------------------------------------------------
__global__ __launch_bounds__(256)
void prep_wo(const float* __restrict__ wo) {
    __shared__ float ts[32 * 136];
    int e = blockIdx.z;
    int n0 = blockIdx.x * 128, k0 = blockIdx.y * 32;
    const float* s = wo + ((size_t)e * I_DIM + k0) * H_DIM + n0;
    int t = threadIdx.x;
#pragma unroll
    for (int i = 0; i < 16; i++) {
        int f = t + 256 * i;
        int r = f >> 7, c = f & 127;
        ts[r * 136 + c] = s[(size_t)r * H_DIM + c];
    }
    __syncthreads();
    uint32_t* d = g_woP + (((size_t)e * NT2 + blockIdx.x) * KI2 + blockIdx.y) * 4096;
    permute_store(ts, d, t);
}

// ---------------------------------------------------------------------------
// GEMM core: 128x128x32 tf32, 3-stage TMA-bulk pipeline, full/empty mbarriers,
// rotating refill warp, A+B fragment double buffering. 96KB -> 2 CTA/SM.
// mbs: full[s] at +8s; empty[s] at +24+8s.
// ---------------------------------------------------------------------------
#define STG_B 32768

struct MmaCtx {
    uint32_t sbase;
    int lane, wm, wn;
};

__device__ __forceinline__ void ld_a4(uint4* af, uint32_t aB, int kk,
                                      int wm, int lane) {
#pragma unroll
    for (int mt = 0; mt < 4; mt++) {
        uint32_t addr = aB + (((kk * 8 + wm * 4 + mt) * 32 + lane) << 4);
        asm volatile("ld.shared.v4.b32 {%0,%1,%2,%3}, [%4];"
                     : "=r"(af[mt].x), "=r"(af[mt].y),
                       "=r"(af[mt].z), "=r"(af[mt].w) : "r"(addr));
    }
}
__device__ __forceinline__ void ld_b4(uint2* bf, uint32_t bB, int kk,
                                      int wn, int lane) {
#pragma unroll
    for (int nt = 0; nt < 4; nt++) {
        uint32_t addr = bB + (((kk * 16 + wn * 4 + nt) * 32 + lane) << 3);
        asm volatile("ld.shared.v2.b32 {%0,%1}, [%2];"
                     : "=r"(bf[nt].x), "=r"(bf[nt].y) : "r"(addr));
    }
}

__device__ __forceinline__ void consume_stage(const MmaCtx& cx, int s,
                                              float acc[4][4][4]) {
    uint32_t aB = cx.sbase + s * STG_B;
    uint32_t bB = aB + 16384;
    uint4 af[2][4];
    uint2 bf[2][4];
    ld_a4(af[0], aB, 0, cx.wm, cx.lane);
    ld_b4(bf[0], bB, 0, cx.wn, cx.lane);
#pragma unroll
    for (int kk = 0; kk < 4; kk++) {
        int cur = kk & 1;
        if (kk < 3) {
            ld_a4(af[cur ^ 1], aB, kk + 1, cx.wm, cx.lane);
            ld_b4(bf[cur ^ 1], bB, kk + 1, cx.wn, cx.lane);
        }
#pragma unroll
        for (int mt = 0; mt < 4; mt++)
#pragma unroll
            for (int nt = 0; nt < 4; nt++)
                mma_tf32(acc[mt][nt], af[cur][mt].x, af[cur][mt].y,
                         af[cur][mt].z, af[cur][mt].w,
                         bf[cur][nt].x, bf[cur][nt].y);
    }
}

// refill stage s with k-iter `it` tiles via 2 bulk copies (single thread)
__device__ __forceinline__ void fill_stage(uint32_t sbase, uint32_t mbar_base,
                                           int s, const uint32_t* aSrc,
                                           const uint32_t* bSrc, int it) {
    uint32_t mb = mbar_base + s * 8;
    uint32_t st = sbase + s * STG_B;
    mbar_expect(mb, 32768);
    bulk_g2s(st,         aSrc + (size_t)it * 4096, 16384, mb);
    bulk_g2s(st + 16384, bSrc + (size_t)it * 4096, 16384, mb);
}

// shared mainloop: full/empty mbarrier pipeline, refill warp rotates (it&7)
template <int KI>
__device__ __forceinline__ void gemm_mainloop(const MmaCtx& cx, uint32_t mbb,
                                              const uint32_t* aSrc,
                                              const uint32_t* bSrc,
                                              int t, float acc[4][4][4]) {
    if (t == 0) {
#pragma unroll
        for (int s = 0; s < 3; s++) {
            mbar_init(mbb + s * 8, 1);        // full: tx-based
            mbar_init(mbb + 24 + s * 8, 8);   // empty: 8 warp arrivals
        }
    }
    __syncthreads();
    if (t == 0) {
#pragma unroll
        for (int p = 0; p < 3; p++) fill_stage(cx.sbase, mbb, p, aSrc, bSrc, p);
    }
    int w = t >> 5;
    for (int it = 0; it < KI; ++it) {
        int s = it % 3;
        uint32_t ph = (uint32_t)((it / 3) & 1);
        mbar_wait(mbb + s * 8, ph);
        consume_stage(cx, s, acc);
        if (cx.lane == 0) mbar_arrive(mbb + 24 + s * 8);
        if (it + 3 < KI && w == (it & 7) && cx.lane == 0) {
            mbar_wait(mbb + 24 + s * 8, ph);      // all 8 warps drained stage s
            fill_stage(cx.sbase, mbb, s, aSrc, bSrc, it + 3);
        }
    }
}

// ---------------------------------------------------------------------------
// Launch 4 (ncu slot): GEMM1: g_aP @ g_wiP -> gelu -> g_hP. mT fastest.
// Triggers dependent launch (prep_wo) at entry so it fills gemm1's tail.
// ---------------------------------------------------------------------------
__global__ __launch_bounds__(256, 2)
void gemm1_tc(float* dummy) {
    extern __shared__ char smem[];
    __shared__ __align__(8) uint64_t mbs[6];

    // allow the PDL-dependent prep_wo to launch once all blocks reached here
    asm volatile("griddepcontrol.launch_dependents;" ::: "memory");

    uint32_t sbase = smem_u32(smem);
    uint32_t mbb   = smem_u32(mbs);

    int e = blockIdx.z;
    int cnt = g_counts[e];
    int mT = blockIdx.x;
    if (mT * 128 >= cnt) return;
    int nT = blockIdx.y;

    int t = threadIdx.x;
    MmaCtx cx;
    cx.sbase = sbase;
    cx.lane = t & 31;
    int w = t >> 5;
    cx.wm = w >> 2; cx.wn = w & 3;

    const uint32_t* aSrc = g_aP  + (((size_t)e * MT_N + mT) * KI1) * 4096;
    const uint32_t* bSrc = g_wiP + (((size_t)e * NT1 + nT) * KI1) * 4096;

    float acc[4][4][4];
#pragma unroll
    for (int a = 0; a < 4; a++)
#pragma unroll
        for (int b = 0; b < 4; b++)
#pragma unroll
            for (int c = 0; c < 4; c++) acc[a][b][c] = 0.f;

    gemm_mainloop<KI1>(cx, mbb, aSrc, bSrc, t, acc);
    __syncthreads();   // all warps done with all stages before smem reuse

    // epilogue: gelu -> fragment-permuted g_hP via smem bounce (128x68 f32)
    float* eb = (float*)smem;
    int ln = cx.lane;
    int rr = ln >> 2, bb = ln & 3;
#pragma unroll
    for (int half = 0; half < 2; half++) {
        if ((cx.wn >> 1) == half) {
            int colbase = (cx.wn & 1) * 32;
#pragma unroll
            for (int mt = 0; mt < 4; mt++) {
                int row = cx.wm * 64 + mt * 16 + rr;
#pragma unroll
                for (int nt = 0; nt < 4; nt++) {
                    int col = colbase + nt * 8 + 2 * bb;
                    float2 v0, v1;
                    v0.x = gelu_exact(acc[mt][nt][0]);
                    v0.y = gelu_exact(acc[mt][nt][1]);
                    v1.x = gelu_exact(acc[mt][nt][2]);
                    v1.y = gelu_exact(acc[mt][nt][3]);
                    *(float2*)&eb[row * 68 + col]       = v0;
                    *(float2*)&eb[(row + 8) * 68 + col] = v1;
                }
            }
        }
        __syncthreads();
        int mt8 = t >> 5;
#pragma unroll
        for (int kl = 0; kl < 2; kl++) {
            int kI = nT * 4 + half * 2 + kl;
            uint32_t* d = g_hP + (((size_t)e * MT_N + mT) * KI2 + kI) * 4096;
#pragma unroll
            for (int j = 0; j < 4; j++) {   // j = kk
                int row = mt8 * 16 + rr;
                int c = kl * 32 + j * 8 + bb;
                uint4 v;
                v.x = f2tf32(eb[row * 68 + c]);
                v.y = f2tf32(eb[(row + 8) * 68 + c]);
                v.z = f2tf32(eb[row * 68 + c + 4]);
                v.w = f2tf32(eb[(row + 8) * 68 + c + 4]);
                *(uint4*)(d + (size_t)(t + 256 * j) * 4) = v;
            }
        }
        __syncthreads();
    }
}

// ---------------------------------------------------------------------------
// Launch 6: GEMM2 split-K(2): g_hP @ g_woP -> weight-scaled atomicAdd to out.
// grid (MT_N, NT2, 2*N_EXP): z = 2e+kh; each half does 128 k-iters.
// Each output element receives exactly 2 float atomics (commutative -> det.)
// ---------------------------------------------------------------------------
__global__ __launch_bounds__(256, 2)
void gemm2_tc(float* __restrict__ outp) {
    extern __shared__ char smem[];
    __shared__ __align__(8) uint64_t mbs[6];
    uint32_t sbase = smem_u32(smem);
    uint32_t mbb   = smem_u32(mbs);

    int ez = blockIdx.z;
    int e  = ez >> 1;
    int kh = ez & 1;
    int cnt = g_counts[e];
    int mT = blockIdx.x;
    if (mT * 128 >= cnt) return;
    int nT = blockIdx.y;
    int n0 = nT * 128;

    int t = threadIdx.x;
    MmaCtx cx;
    cx.sbase = sbase;
    cx.lane = t & 31;
    int w = t >> 5;
    cx.wm = w >> 2; cx.wn = w & 3;

    const uint32_t* aSrc = g_hP + (((size_t)e * MT_N + mT) * KI2
                                   + (size_t)kh * KH2) * 4096;
    const uint32_t* bSrc = g_woP + (((size_t)e * NT2 + nT) * KI2
                                    + (size_t)kh * KH2) * 4096;

    float acc[4][4][4];
#pragma unroll
    for (int a = 0; a < 4; a++)
#pragma unroll
        for (int b = 0; b < 4; b++)
#pragma unroll
            for (int c = 0; c < 4; c++) acc[a][b][c] = 0.f;

    gemm_mainloop<KH2>(cx, mbb, aSrc, bSrc, t, acc);

    // epilogue: weight * acc atomically accumulated into out rows
    int ln = cx.lane;
    int rr = ln >> 2, bb = ln & 3;
    int m0 = mT * 128;
#pragma unroll
    for (int mt = 0; mt < 4; mt++) {
#pragma unroll
        for (int h = 0; h < 2; h++) {
            int m = m0 + cx.wm * 64 + mt * 16 + rr + 8 * h;
            int tok = g_token_of_slot[e * CAP + m];
            if (tok < 0) continue;
            float wgt = g_slot_wt[e * CAP + m];
            float* orow = outp + (size_t)tok * H_DIM + n0 + cx.wn * 32;
#pragma unroll
            for (int nt = 0; nt < 4; nt++) {
                atomicAdd(&orow[nt * 8 + 2 * bb],     wgt * acc[mt][nt][2 * h]);
                atomicAdd(&orow[nt * 8 + 2 * bb + 1], wgt * acc[mt][nt][2 * h + 1]);
            }
        }
    }
}

extern "C" void kernel_launch(void* const* d_in, const int* in_sizes, int n_in,
                              void* d_out, int out_size) {
    const float* tokens = (const float*)d_in[0];
    const float* gw     = (const float*)d_in[1];
    const float* wi     = (const float*)d_in[2];
    const float* wo     = (const float*)d_in[3];
    float* outp = (float*)d_out;

    const int SMEM = 3 * STG_B;   // 98304 -> 2 CTA/SM
    cudaFuncSetAttribute(gemm1_tc, cudaFuncAttributeMaxDynamicSharedMemorySize, SMEM);
    cudaFuncSetAttribute(gemm2_tc, cudaFuncAttributeMaxDynamicSharedMemorySize, SMEM);

    prep_wi_gate<<<PWI_BLKS + GATE_BLKS + ZERO_BLKS, 256>>>(tokens, gw, wi, outp); // 1
    rank_kernel<<<1, 1024>>>();                                                    // 2
    dispatch_aP<<<dim3(KI1, MT_N, N_EXP), 256>>>(tokens);                          // 3
    gemm1_tc<<<dim3(MT_N, NT1, N_EXP), 256, SMEM>>>(nullptr);                      // 4

    // prep_wo overlaps gemm1's tail via programmatic stream serialization
    {
        cudaLaunchConfig_t cfg = {};
        cfg.gridDim  = dim3(NT2, KI2, N_EXP);
        cfg.blockDim = dim3(256, 1, 1);
        cfg.dynamicSmemBytes = 0;
        cfg.stream = 0;
        cudaLaunchAttribute attr[1];
        attr[0].id = cudaLaunchAttributeProgrammaticStreamSerialization;
        attr[0].val.programmaticStreamSerializationAllowed = 1;
        cfg.attrs = attr;
        cfg.numAttrs = 1;
        cudaLaunchKernelEx(&cfg, prep_wo, wo);                                     // 5
    }

    gemm2_tc<<<dim3(MT_N, NT2, 2 * N_EXP), 256, SMEM>>>(outp);                     // 6
}